// round 7
// baseline (speedup 1.0000x reference)
#include <cuda_runtime.h>
#include <mma.h>
#include <cstdint>

using namespace nvcuda;

// Problem dims
#define BATCH 4096
#define TSTEPS 365
#define FDIM 16
#define MT 32              // batch rows per CTA
#define NCTA (BATCH/MT)    // 128
#define KAUG 272           // 256 (h) + 16 (x)
#define NCHUNK 34          // 272 / 8

// SMEM layout (floats)
#define LDH 280            // h row stride (272 + 8 pad)
#define WB_LD 132          // W chunk row stride (128 + 4 pad)
#define SCR_LD 132         // gate scratch row stride

#define OFF_H    0                         // 32 x 280
#define OFF_HE   (OFF_H + MT*LDH)          // 8960  (32 x 260, exact h, final step only)
#define OFF_BIAS (OFF_HE + MT*260)         // 17280
#define OFF_WOUT (OFF_BIAS + 1024)         // 18304
#define OFF_SH   (OFF_WOUT + 640)          // 18944 (8 x 2112: per-cg W dbl-buf / scratch)
#define SMEM_FLOATS (OFF_SH + 8*2112)      // 35840 floats = 143360 B

// ---------------- device globals (preprocessed weights) ----------------
// g_Waug[k][n'] : rows 0..255 = W_hh^T, rows 256..271 = W_ih^T
// n' gate-interleaved (n' = j*4 + gate), tf32-rounded
__device__ float g_Waug[KAUG * 1024];
__device__ float g_biasP[1024];

__global__ void prep_kernel(const float* __restrict__ W_ih,
                            const float* __restrict__ W_hh,
                            const float* __restrict__ b_ih,
                            const float* __restrict__ b_hh) {
    int tid = blockIdx.x * blockDim.x + threadIdx.x;
    int stride = gridDim.x * blockDim.x;
    for (int o = tid; o < KAUG * 1024; o += stride) {
        int k = o >> 10, np = o & 1023;
        int gate = np & 3, j = np >> 2;
        int n = gate * 256 + j;
        float v = (k < 256) ? W_hh[n * 256 + k] : W_ih[n * 16 + (k - 256)];
        g_Waug[o] = wmma::__float_to_tf32(v);
    }
    for (int o = tid; o < 1024; o += stride) {
        int gate = o & 3, j = o >> 2;
        int n = gate * 256 + j;
        g_biasP[o] = b_ih[n] + b_hh[n];
    }
}

// ---------------- helpers ----------------
__device__ __forceinline__ void cp_async16(float* smem_dst, const float* gsrc) {
    unsigned saddr = (unsigned)__cvta_generic_to_shared(smem_dst);
    asm volatile("cp.async.cg.shared.global [%0], [%1], 16;\n" :: "r"(saddr), "l"(gsrc));
}
__device__ __forceinline__ void cp_commit() {
    asm volatile("cp.async.commit_group;\n");
}
__device__ __forceinline__ void cp_wait0() {
    asm volatile("cp.async.wait_group 0;\n");
}
__device__ __forceinline__ void cp_wait1() {
    asm volatile("cp.async.wait_group 1;\n");
}
__device__ __forceinline__ void bar_named(int id, int cnt) {
    asm volatile("bar.sync %0, %1;" :: "r"(id), "r"(cnt) : "memory");
}

// sigmoid via HW tanh: 1 MUFU + 2 FMA
__device__ __forceinline__ float sig_approx(float x) {
    float t;
    asm("tanh.approx.f32 %0, %1;" : "=f"(t) : "f"(0.5f * x));
    return fmaf(0.5f, t, 0.5f);
}
// accurate tanh (EX2 + RCP): used where error feeds output directly
__device__ __forceinline__ float tanhf_fast(float x) {
    x = fminf(fmaxf(x, -15.f), 15.f);
    float e = __expf(-2.f * x);
    return __fdividef(1.f - e, 1.f + e);
}

// stage half (4 rows) of an 8x128 W chunk: warp rb stages rows rb*4..rb*4+4
__device__ __forceinline__ void stage_half(float* wbuf, int kc, int cg, int rb, int ln) {
#pragma unroll
    for (int it = 0; it < 4; ++it) {
        int kr = rb * 4 + it;
        cp_async16(wbuf + kr * WB_LD + ln * 4,
                   &g_Waug[(size_t)(kc * 8 + kr) * 1024 + cg * 128 + ln * 4]);
    }
}

// ---------------- main persistent LSTM kernel ----------------
__global__ void __launch_bounds__(512, 1)
lstm_kernel(const float* __restrict__ w,
            const float* __restrict__ W_out,
            const float* __restrict__ b_out,
            float* __restrict__ out) {
    extern __shared__ float sm[];
    float* h_tf   = sm + OFF_H;     // [32][LDH]: cols 0..255 = h (tf32), 256..271 = x_t (tf32)
    float* h_ex   = sm + OFF_HE;    // exact h, written at final step only
    float* bias_sm= sm + OFF_BIAS;
    float* wout_sm= sm + OFF_WOUT;
    float* shreg  = sm + OFF_SH;    // per-cg W dbl-buffers / gate scratch (aliased)

    const int tid = threadIdx.x;
    const int wp  = tid >> 5;
    const int ln  = tid & 31;
    const int cg  = wp & 7;         // col-slice: perm cols [cg*128, cg*128+128) = units [cg*32,+32)
    const int rb  = wp >> 3;        // row-tile: rows [rb*16, rb*16+16)
    const int b0  = blockIdx.x * MT;
    const int barid = 1 + cg;

    // init
    for (int i = tid; i < MT * LDH; i += 512) h_tf[i] = 0.f;
    for (int i = tid; i < 1024; i += 512) bias_sm[i] = g_biasP[i];
    if (tid < 512) { if (tid < 512) {} }
    for (int i = tid; i < 512; i += 512) wout_sm[i] = W_out[i];
    if (tid < 2) wout_sm[512 + tid] = b_out[tid];
    __syncthreads();

    float* wbuf0 = shreg + cg * 2112;   // 8 x WB_LD
    float* wbuf1 = wbuf0 + 1056;
    float* scr   = wbuf0;               // 16 x SCR_LD aliases the dbl-buffer

    // cell state: warp owns 16 rows x 32 units; lane owns 4 rows x 4 units
    float creg[16];
#pragma unroll
    for (int i = 0; i < 16; i++) creg[i] = 0.f;

    const int rbase = (ln >> 3) * 4;    // local row base (0,4,8,12)
    const int ub    = ln & 7;           // unit base (units ub, ub+8, ub+16, ub+24)

    wmma::fragment<wmma::accumulator, 16, 16, 8, float> acc[8];

    for (int t = 0; t < TSTEPS; ++t) {
        // stage x_t into h_tf K-cols 256..271 (tf32) — 512 threads, 1 elem each
        {
            int r = tid >> 4, f = tid & 15;
            h_tf[r * LDH + 256 + f] =
                wmma::__float_to_tf32(w[((size_t)(b0 + r) * TSTEPS + t) * FDIM + f]);
        }
        __syncthreads();  // B0: prev h writes + x visible; scratch reads done

        // prefetch chunk 0
        stage_half(wbuf0, 0, cg, rb, ln);
        cp_commit();

#pragma unroll
        for (int i = 0; i < 8; i++) wmma::fill_fragment(acc[i], 0.f);

        // [h|x] @ Waug : K=272, 34 chunks of 8, cg-shared double buffer
        for (int kc = 0; kc < NCHUNK; ++kc) {
            float* cur = (kc & 1) ? wbuf1 : wbuf0;
            if (kc < NCHUNK - 1) {
                stage_half((kc & 1) ? wbuf0 : wbuf1, kc + 1, cg, rb, ln);
                cp_commit();
                cp_wait1();          // own half of chunk kc complete
            } else {
                cp_wait0();
            }
            bar_named(barid, 64);    // partner's half of chunk kc complete
            wmma::fragment<wmma::matrix_a, 16, 16, 8, wmma::precision::tf32, wmma::row_major> a;
            wmma::load_matrix_sync(a, h_tf + rb * 16 * LDH + kc * 8, LDH);
#pragma unroll
            for (int i = 0; i < 8; i++) {
                wmma::fragment<wmma::matrix_b, 16, 16, 8, wmma::precision::tf32, wmma::row_major> bf;
                wmma::load_matrix_sync(bf, cur + i * 16, WB_LD);
                wmma::mma_sync(acc[i], a, bf, acc[i]);
            }
        }
        bar_named(barid, 64);  // both warps' mma done before scratch overwrites W buf

        // epilogue: rb0 then rb1 phase through the cg-private scratch
#pragma unroll
        for (int ph = 0; ph < 2; ++ph) {
            if (rb == ph) {
#pragma unroll
                for (int i = 0; i < 8; i++)
                    wmma::store_matrix_sync(scr + i * 16, acc[i], SCR_LD, wmma::mem_row_major);
                __syncwarp();
                float4 bv[4];
#pragma unroll
                for (int uu = 0; uu < 4; ++uu)
                    bv[uu] = *reinterpret_cast<const float4*>(bias_sm + (cg * 32 + ub + uu * 8) * 4);
#pragma unroll
                for (int rr = 0; rr < 4; ++rr) {
                    const int rl = rbase + rr;          // local row 0..15
                    const int row = rb * 16 + rl;       // CTA row 0..31
#pragma unroll
                    for (int uu = 0; uu < 4; ++uu) {
                        const int ul = ub + uu * 8;
                        float4 gv = *reinterpret_cast<float4*>(scr + rl * SCR_LD + ul * 4);
                        float gi = sig_approx(gv.x + bv[uu].x);
                        float gf = sig_approx(gv.y + bv[uu].y);
                        float gg = tanhf_fast(gv.z + bv[uu].z);
                        float go = sig_approx(gv.w + bv[uu].w);
                        const int ci = rr * 4 + uu;
                        float c = gf * creg[ci] + gi * gg;
                        creg[ci] = c;
                        float hn = go * tanhf_fast(c);
                        const int jg = cg * 32 + ul;
                        h_tf[row * LDH + jg] = wmma::__float_to_tf32(hn);
                        if (t == TSTEPS - 1) {
                            h_ex[row * 260 + jg] = hn;
                            out[8192 + (size_t)(b0 + row) * 256 + jg] = hn;
                        }
                    }
                }
            }
            bar_named(barid, 64);  // hand scratch to partner / release
        }
    }
    __syncthreads();

    // head: tz0 = ELU(h) @ W_out^T + b_out  (exact fp32)
    if (tid < 64) {
        const int r = tid >> 1, oi = tid & 1;
        float s = wout_sm[512 + oi];
        for (int j = 0; j < 256; ++j) {
            float v = h_ex[r * 260 + j];
            float e = (v > 0.f) ? v : (__expf(v) - 1.f);
            s += e * wout_sm[oi * 256 + j];
        }
        out[(size_t)oi * 4096 + (b0 + r)] = s;
    }
}

// ---------------- launch ----------------
extern "C" void kernel_launch(void* const* d_in, const int* in_sizes, int n_in,
                              void* d_out, int out_size) {
    const float* w     = (const float*)d_in[0];
    const float* W_ih  = (const float*)d_in[1];
    const float* W_hh  = (const float*)d_in[2];
    const float* b_ih  = (const float*)d_in[3];
    const float* b_hh  = (const float*)d_in[4];
    const float* W_out = (const float*)d_in[5];
    const float* b_out = (const float*)d_in[6];
    float* out = (float*)d_out;

    prep_kernel<<<256, 256>>>(W_ih, W_hh, b_ih, b_hh);

    const int smem_bytes = SMEM_FLOATS * sizeof(float);  // 143360 B
    cudaFuncSetAttribute(lstm_kernel, cudaFuncAttributeMaxDynamicSharedMemorySize, smem_bytes);
    lstm_kernel<<<NCTA, 512, smem_bytes>>>(w, W_out, b_out, out);
}

// round 8
// speedup vs baseline: 1.0002x; 1.0002x over previous
#include <cuda_runtime.h>
#include <mma.h>
#include <cstdint>

using namespace nvcuda;

// Problem dims
#define BATCH 4096
#define TSTEPS 365
#define FDIM 16
#define MT 32              // batch rows per CTA
#define NCTA (BATCH/MT)    // 128
#define KAUG 272           // 256 (h) + 16 (x)
#define NCHUNK 34          // 272 / 8

// SMEM layout (floats)
#define LDH 280            // h row stride (272 + 8 pad)
#define WB_LD 132          // W chunk row stride (128 + 4 pad)
#define SCR_LD 132         // gate scratch row stride

#define OFF_H    0                         // 32 x 280
#define OFF_HE   (OFF_H + MT*LDH)          // 8960  (32 x 260, exact h, final step only)
#define OFF_BIAS (OFF_HE + MT*260)         // 17280
#define OFF_WOUT (OFF_BIAS + 1024)         // 18304
#define OFF_SH   (OFF_WOUT + 640)          // 18944 (8 x 2112: per-cg W dbl-buf / scratch)
#define SMEM_FLOATS (OFF_SH + 8*2112)      // 35840 floats = 143360 B

// ---------------- device globals (preprocessed weights) ----------------
// g_Waug[k][n'] : rows 0..255 = W_hh^T, rows 256..271 = W_ih^T
// n' gate-interleaved (n' = j*4 + gate), tf32-rounded
__device__ float g_Waug[KAUG * 1024];
__device__ float g_biasP[1024];

__global__ void prep_kernel(const float* __restrict__ W_ih,
                            const float* __restrict__ W_hh,
                            const float* __restrict__ b_ih,
                            const float* __restrict__ b_hh) {
    int tid = blockIdx.x * blockDim.x + threadIdx.x;
    int stride = gridDim.x * blockDim.x;
    for (int o = tid; o < KAUG * 1024; o += stride) {
        int k = o >> 10, np = o & 1023;
        int gate = np & 3, j = np >> 2;
        int n = gate * 256 + j;
        float v = (k < 256) ? W_hh[n * 256 + k] : W_ih[n * 16 + (k - 256)];
        g_Waug[o] = wmma::__float_to_tf32(v);
    }
    for (int o = tid; o < 1024; o += stride) {
        int gate = o & 3, j = o >> 2;
        int n = gate * 256 + j;
        g_biasP[o] = b_ih[n] + b_hh[n];
    }
}

// ---------------- helpers ----------------
__device__ __forceinline__ void cp_async16(float* smem_dst, const float* gsrc) {
    unsigned saddr = (unsigned)__cvta_generic_to_shared(smem_dst);
    asm volatile("cp.async.cg.shared.global [%0], [%1], 16;\n" :: "r"(saddr), "l"(gsrc));
}
__device__ __forceinline__ void cp_commit() {
    asm volatile("cp.async.commit_group;\n");
}
__device__ __forceinline__ void cp_wait0() {
    asm volatile("cp.async.wait_group 0;\n");
}
__device__ __forceinline__ void cp_wait1() {
    asm volatile("cp.async.wait_group 1;\n");
}
__device__ __forceinline__ void bar_named(int id, int cnt) {
    asm volatile("bar.sync %0, %1;" :: "r"(id), "r"(cnt) : "memory");
}

// sigmoid via HW tanh: 1 MUFU + 2 FMA
__device__ __forceinline__ float sig_approx(float x) {
    float t;
    asm("tanh.approx.f32 %0, %1;" : "=f"(t) : "f"(0.5f * x));
    return fmaf(0.5f, t, 0.5f);
}
// accurate tanh (EX2 + RCP): used where error feeds output directly
__device__ __forceinline__ float tanhf_fast(float x) {
    x = fminf(fmaxf(x, -15.f), 15.f);
    float e = __expf(-2.f * x);
    return __fdividef(1.f - e, 1.f + e);
}

// stage half (4 rows) of an 8x128 W chunk: warp rb stages rows rb*4..rb*4+4
__device__ __forceinline__ void stage_half(float* wbuf, int kc, int cg, int rb, int ln) {
#pragma unroll
    for (int it = 0; it < 4; ++it) {
        int kr = rb * 4 + it;
        cp_async16(wbuf + kr * WB_LD + ln * 4,
                   &g_Waug[(size_t)(kc * 8 + kr) * 1024 + cg * 128 + ln * 4]);
    }
}

// ---------------- main persistent LSTM kernel ----------------
__global__ void __launch_bounds__(512, 1)
lstm_kernel(const float* __restrict__ w,
            const float* __restrict__ W_out,
            const float* __restrict__ b_out,
            float* __restrict__ out) {
    extern __shared__ float sm[];
    float* h_tf   = sm + OFF_H;     // [32][LDH]: cols 0..255 = h (tf32), 256..271 = x_t (tf32)
    float* h_ex   = sm + OFF_HE;    // exact h, written at final step only
    float* bias_sm= sm + OFF_BIAS;
    float* wout_sm= sm + OFF_WOUT;
    float* shreg  = sm + OFF_SH;    // per-cg W dbl-buffers / gate scratch (aliased)

    const int tid = threadIdx.x;
    const int wp  = tid >> 5;
    const int ln  = tid & 31;
    const int cg  = wp & 7;         // col-slice: perm cols [cg*128, cg*128+128) = units [cg*32,+32)
    const int rb  = wp >> 3;        // row-tile: rows [rb*16, rb*16+16)
    const int b0  = blockIdx.x * MT;
    const int barid = 1 + cg;

    // init
    for (int i = tid; i < MT * LDH; i += 512) h_tf[i] = 0.f;
    for (int i = tid; i < 1024; i += 512) bias_sm[i] = g_biasP[i];
    if (tid < 512) { if (tid < 512) {} }
    for (int i = tid; i < 512; i += 512) wout_sm[i] = W_out[i];
    if (tid < 2) wout_sm[512 + tid] = b_out[tid];
    __syncthreads();

    float* wbuf0 = shreg + cg * 2112;   // 8 x WB_LD
    float* wbuf1 = wbuf0 + 1056;
    float* scr   = wbuf0;               // 16 x SCR_LD aliases the dbl-buffer

    // cell state: warp owns 16 rows x 32 units; lane owns 4 rows x 4 units
    float creg[16];
#pragma unroll
    for (int i = 0; i < 16; i++) creg[i] = 0.f;

    const int rbase = (ln >> 3) * 4;    // local row base (0,4,8,12)
    const int ub    = ln & 7;           // unit base (units ub, ub+8, ub+16, ub+24)

    wmma::fragment<wmma::accumulator, 16, 16, 8, float> acc[8];

    for (int t = 0; t < TSTEPS; ++t) {
        // stage x_t into h_tf K-cols 256..271 (tf32) — 512 threads, 1 elem each
        {
            int r = tid >> 4, f = tid & 15;
            h_tf[r * LDH + 256 + f] =
                wmma::__float_to_tf32(w[((size_t)(b0 + r) * TSTEPS + t) * FDIM + f]);
        }
        __syncthreads();  // B0: prev h writes + x visible; scratch reads done

        // prefetch chunk 0
        stage_half(wbuf0, 0, cg, rb, ln);
        cp_commit();

#pragma unroll
        for (int i = 0; i < 8; i++) wmma::fill_fragment(acc[i], 0.f);

        // [h|x] @ Waug : K=272, 34 chunks of 8, cg-shared double buffer
        for (int kc = 0; kc < NCHUNK; ++kc) {
            float* cur = (kc & 1) ? wbuf1 : wbuf0;
            if (kc < NCHUNK - 1) {
                stage_half((kc & 1) ? wbuf0 : wbuf1, kc + 1, cg, rb, ln);
                cp_commit();
                cp_wait1();          // own half of chunk kc complete
            } else {
                cp_wait0();
            }
            bar_named(barid, 64);    // partner's half of chunk kc complete
            wmma::fragment<wmma::matrix_a, 16, 16, 8, wmma::precision::tf32, wmma::row_major> a;
            wmma::load_matrix_sync(a, h_tf + rb * 16 * LDH + kc * 8, LDH);
#pragma unroll
            for (int i = 0; i < 8; i++) {
                wmma::fragment<wmma::matrix_b, 16, 16, 8, wmma::precision::tf32, wmma::row_major> bf;
                wmma::load_matrix_sync(bf, cur + i * 16, WB_LD);
                wmma::mma_sync(acc[i], a, bf, acc[i]);
            }
        }
        bar_named(barid, 64);  // both warps' mma done before scratch overwrites W buf

        // epilogue: rb0 then rb1 phase through the cg-private scratch
#pragma unroll
        for (int ph = 0; ph < 2; ++ph) {
            if (rb == ph) {
#pragma unroll
                for (int i = 0; i < 8; i++)
                    wmma::store_matrix_sync(scr + i * 16, acc[i], SCR_LD, wmma::mem_row_major);
                __syncwarp();
                float4 bv[4];
#pragma unroll
                for (int uu = 0; uu < 4; ++uu)
                    bv[uu] = *reinterpret_cast<const float4*>(bias_sm + (cg * 32 + ub + uu * 8) * 4);
#pragma unroll
                for (int rr = 0; rr < 4; ++rr) {
                    const int rl = rbase + rr;          // local row 0..15
                    const int row = rb * 16 + rl;       // CTA row 0..31
#pragma unroll
                    for (int uu = 0; uu < 4; ++uu) {
                        const int ul = ub + uu * 8;
                        float4 gv = *reinterpret_cast<float4*>(scr + rl * SCR_LD + ul * 4);
                        float gi = sig_approx(gv.x + bv[uu].x);
                        float gf = sig_approx(gv.y + bv[uu].y);
                        float gg = tanhf_fast(gv.z + bv[uu].z);
                        float go = sig_approx(gv.w + bv[uu].w);
                        const int ci = rr * 4 + uu;
                        float c = gf * creg[ci] + gi * gg;
                        creg[ci] = c;
                        float hn = go * tanhf_fast(c);
                        const int jg = cg * 32 + ul;
                        h_tf[row * LDH + jg] = wmma::__float_to_tf32(hn);
                        if (t == TSTEPS - 1) {
                            h_ex[row * 260 + jg] = hn;
                            out[8192 + (size_t)(b0 + row) * 256 + jg] = hn;
                        }
                    }
                }
            }
            bar_named(barid, 64);  // hand scratch to partner / release
        }
    }
    __syncthreads();

    // head: tz0 = ELU(h) @ W_out^T + b_out  (exact fp32)
    if (tid < 64) {
        const int r = tid >> 1, oi = tid & 1;
        float s = wout_sm[512 + oi];
        for (int j = 0; j < 256; ++j) {
            float v = h_ex[r * 260 + j];
            float e = (v > 0.f) ? v : (__expf(v) - 1.f);
            s += e * wout_sm[oi * 256 + j];
        }
        out[(size_t)oi * 4096 + (b0 + r)] = s;
    }
}

// ---------------- launch ----------------
extern "C" void kernel_launch(void* const* d_in, const int* in_sizes, int n_in,
                              void* d_out, int out_size) {
    const float* w     = (const float*)d_in[0];
    const float* W_ih  = (const float*)d_in[1];
    const float* W_hh  = (const float*)d_in[2];
    const float* b_ih  = (const float*)d_in[3];
    const float* b_hh  = (const float*)d_in[4];
    const float* W_out = (const float*)d_in[5];
    const float* b_out = (const float*)d_in[6];
    float* out = (float*)d_out;

    prep_kernel<<<256, 256>>>(W_ih, W_hh, b_ih, b_hh);

    const int smem_bytes = SMEM_FLOATS * sizeof(float);  // 143360 B
    cudaFuncSetAttribute(lstm_kernel, cudaFuncAttributeMaxDynamicSharedMemorySize, smem_bytes);
    lstm_kernel<<<NCTA, 512, smem_bytes>>>(w, W_out, b_out, out);
}

// round 10
// speedup vs baseline: 2.5326x; 2.5321x over previous
#include <cuda_runtime.h>
#include <cuda_fp16.h>
#include <mma.h>
#include <cstdint>

using namespace nvcuda;

// Problem dims
#define BATCH 4096
#define TSTEPS 365
#define FDIM 16
#define MT 32              // batch rows per CTA
#define NCTA (BATCH/MT)    // 128
#define KAUG 272           // 256 (h) + 16 (x)
#define NCHUNK 17          // 272 / 16

// strides (elements)
#define LDHH 280           // h row stride in halves (272 + 8 pad)
#define WBH  136           // W chunk row stride in halves (128 + 8 pad)
#define SCR_LD 132         // gate scratch row stride (floats)

// SMEM byte offsets (16B aligned)
#define OFF_HH   0                     // 32 x 280 halves = 17920
#define OFF_HEX  17920                 // 32 x 260 floats = 33280 (final step only)
#define OFF_BIAS 51200                 // 1024 floats
#define OFF_WOUT 55296                 // 520 floats (512 W_out + 2 b_out)
#define OFF_SH   57376                 // per-warp W dbl-buf (8x2x16x136 halves = 69632 B)
                                       //   aliased with 4 scratch slots (4x32x132 f = 67584 B)
#define SMEM_BYTES (OFF_SH + 69632)    // 127008

// ---------------- device globals (preprocessed weights) ----------------
// g_Waug[k][n'] : rows 0..255 = W_hh^T, rows 256..271 = W_ih^T
// n' gate-interleaved (n' = j*4 + gate), fp16
__device__ __align__(256) __half g_Waug[KAUG * 1024];
__device__ float g_biasP[1024];

__global__ void prep_kernel(const float* __restrict__ W_ih,
                            const float* __restrict__ W_hh,
                            const float* __restrict__ b_ih,
                            const float* __restrict__ b_hh) {
    int tid = blockIdx.x * blockDim.x + threadIdx.x;
    int stride = gridDim.x * blockDim.x;
    for (int o = tid; o < KAUG * 1024; o += stride) {
        int k = o >> 10, np = o & 1023;
        int gate = np & 3, j = np >> 2;
        int n = gate * 256 + j;
        float v = (k < 256) ? W_hh[n * 256 + k] : W_ih[n * 16 + (k - 256)];
        g_Waug[o] = __float2half_rn(v);
    }
    for (int o = tid; o < 1024; o += stride) {
        int gate = o & 3, j = o >> 2;
        int n = gate * 256 + j;
        g_biasP[o] = b_ih[n] + b_hh[n];
    }
}

// ---------------- helpers ----------------
__device__ __forceinline__ void cp_async16(void* smem_dst, const void* gsrc) {
    unsigned saddr = (unsigned)__cvta_generic_to_shared(smem_dst);
    asm volatile("cp.async.cg.shared.global [%0], [%1], 16;\n" :: "r"(saddr), "l"(gsrc));
}
__device__ __forceinline__ void cp_commit() { asm volatile("cp.async.commit_group;\n"); }
__device__ __forceinline__ void cp_wait0()  { asm volatile("cp.async.wait_group 0;\n"); }
__device__ __forceinline__ void cp_wait1()  { asm volatile("cp.async.wait_group 1;\n"); }

// sigmoid via HW tanh: 1 MUFU + 2 FMA
__device__ __forceinline__ float sig_approx(float x) {
    float t;
    asm("tanh.approx.f32 %0, %1;" : "=f"(t) : "f"(0.5f * x));
    return fmaf(0.5f, t, 0.5f);
}
// accurate tanh (EX2 + RCP): used where error feeds output directly
__device__ __forceinline__ float tanhf_fast(float x) {
    x = fminf(fmaxf(x, -15.f), 15.f);
    float e = __expf(-2.f * x);
    return __fdividef(1.f - e, 1.f + e);
}

// stage one 16x128 fp16 W chunk (warp-private slice) via cp.async: 4KB, 8x16B per lane
__device__ __forceinline__ void stage_chunk(__half* wbuf, int kc, int wp, int ln) {
#pragma unroll
    for (int it = 0; it < 8; ++it) {
        int lin = it * 32 + ln;          // 0..255
        int row = lin >> 4;              // 0..15
        int c8  = lin & 15;              // 0..15 (8-half groups)
        cp_async16(wbuf + row * WBH + c8 * 8,
                   &g_Waug[(size_t)(kc * 16 + row) * 1024 + wp * 128 + c8 * 8]);
    }
}

// ---------------- main persistent LSTM kernel ----------------
__global__ void __launch_bounds__(256, 1)
lstm_kernel(const float* __restrict__ w,
            const float* __restrict__ W_out,
            const float* __restrict__ b_out,
            float* __restrict__ out) {
    extern __shared__ char smb[];
    __half* h_h    = (__half*)(smb + OFF_HH);   // [32][LDHH]: cols 0..255 = h, 256..271 = x_t
    float*  h_ex   = (float*)(smb + OFF_HEX);   // exact h, final step only
    float*  bias_sm= (float*)(smb + OFF_BIAS);
    float*  wout_sm= (float*)(smb + OFF_WOUT);
    char*   shreg  = smb + OFF_SH;              // W dbl-bufs / gate scratch (aliased)

    const int tid = threadIdx.x;
    const int wp  = tid >> 5;
    const int ln  = tid & 31;
    const int b0  = blockIdx.x * MT;

    // init
    for (int i = tid; i < MT * LDHH; i += 256) h_h[i] = __float2half_rn(0.f);
    for (int i = tid; i < 1024; i += 256) bias_sm[i] = g_biasP[i];
    for (int i = tid; i < 512; i += 256) wout_sm[i] = W_out[i];
    if (tid < 2) wout_sm[512 + tid] = b_out[tid];
    __syncthreads();

    // warp wp owns: all 32 rows x perm cols [wp*128, +128) = hidden units [wp*32, +32)
    const int phase = wp >> 2;                   // each phase: 4 warps on 4 distinct SMSPs
    const int slot  = wp & 3;
    float*  scr   = (float*)(shreg + slot * 16896);  // 32 x SCR_LD floats
    __half* wbuf0 = (__half*)(shreg + wp * 8704);    // 16 x WBH halves
    __half* wbuf1 = wbuf0 + 16 * WBH;

    // cell state: lane owns 8 rows x 4 units = 32 cells
    float creg[32];
#pragma unroll
    for (int i = 0; i < 32; i++) creg[i] = 0.f;

    const int rbase = (ln >> 3) * 8;    // local row base (0,8,16,24)
    const int ub    = ln & 7;           // unit base (units ub, ub+8, ub+16, ub+24)

    wmma::fragment<wmma::accumulator, 16, 16, 16, float> acc0[8], acc1[8];

    for (int t = 0; t < TSTEPS; ++t) {
        // stage x_t into h_h K-cols 256..271 (fp16) — 256 threads, 2 elems each
#pragma unroll
        for (int i = tid; i < MT * FDIM; i += 256) {
            int r = i >> 4, f = i & 15;
            h_h[r * LDHH + 256 + f] =
                __float2half_rn(w[((size_t)(b0 + r) * TSTEPS + t) * FDIM + f]);
        }
        __syncthreads();  // B0: prev h writes + x visible; scratch readers done

        // prefetch chunk 0 (warp-private)
        stage_chunk(wbuf0, 0, wp, ln);
        cp_commit();

#pragma unroll
        for (int i = 0; i < 8; i++) { wmma::fill_fragment(acc0[i], 0.f); wmma::fill_fragment(acc1[i], 0.f); }

        // [h|x] @ Waug : K=272, 17 chunks of 16, warp-private double buffer, NO barriers
        for (int kc = 0; kc < NCHUNK; ++kc) {
            __half* cur = (kc & 1) ? wbuf1 : wbuf0;
            if (kc < NCHUNK - 1) {
                stage_chunk((kc & 1) ? wbuf0 : wbuf1, kc + 1, wp, ln);
                cp_commit();
                cp_wait1();          // current chunk complete
            } else {
                cp_wait0();
            }
            __syncwarp();
            wmma::fragment<wmma::matrix_a, 16, 16, 16, __half, wmma::row_major> a0, a1;
            wmma::load_matrix_sync(a0, h_h + kc * 16, LDHH);
            wmma::load_matrix_sync(a1, h_h + 16 * LDHH + kc * 16, LDHH);
#pragma unroll
            for (int i = 0; i < 8; i++) {
                wmma::fragment<wmma::matrix_b, 16, 16, 16, __half, wmma::row_major> bf;
                wmma::load_matrix_sync(bf, cur + i * 16, WBH);
                wmma::mma_sync(acc0[i], a0, bf, acc0[i]);
                wmma::mma_sync(acc1[i], a1, bf, acc1[i]);
            }
        }
        __syncthreads();  // B1: all mma done before scratch overwrites W buffers

        // epilogue: 2 phases x 4 warps (one per SMSP each phase)
#pragma unroll
        for (int ph = 0; ph < 2; ++ph) {
            if (phase == ph) {
#pragma unroll
                for (int i = 0; i < 8; i++) {
                    wmma::store_matrix_sync(scr + i * 16, acc0[i], SCR_LD, wmma::mem_row_major);
                    wmma::store_matrix_sync(scr + 16 * SCR_LD + i * 16, acc1[i], SCR_LD, wmma::mem_row_major);
                }
                __syncwarp();
                float4 bv[4];
#pragma unroll
                for (int uu = 0; uu < 4; ++uu)
                    bv[uu] = *reinterpret_cast<const float4*>(bias_sm + (wp * 32 + ub + uu * 8) * 4);
#pragma unroll
                for (int rr = 0; rr < 8; ++rr) {
                    const int r = rbase + rr;
#pragma unroll
                    for (int uu = 0; uu < 4; ++uu) {
                        const int ul = ub + uu * 8;
                        float4 gv = *reinterpret_cast<float4*>(scr + r * SCR_LD + ul * 4);
                        float gi = sig_approx(gv.x + bv[uu].x);
                        float gf = sig_approx(gv.y + bv[uu].y);
                        float gg = tanhf_fast(gv.z + bv[uu].z);
                        float go = sig_approx(gv.w + bv[uu].w);
                        const int ci = rr * 4 + uu;
                        float c = gf * creg[ci] + gi * gg;
                        creg[ci] = c;
                        float hn = go * tanhf_fast(c);
                        const int jg = wp * 32 + ul;
                        h_h[r * LDHH + jg] = __float2half_rn(hn);
                        if (t == TSTEPS - 1) {
                            h_ex[r * 260 + jg] = hn;
                            out[8192 + (size_t)(b0 + r) * 256 + jg] = hn;
                        }
                    }
                }
            }
            __syncthreads();  // B2 / B3
        }
    }

    // head: tz0 = ELU(h) @ W_out^T + b_out  (exact fp32)
    if (tid < 64) {
        const int r = tid >> 1, oi = tid & 1;
        float s = wout_sm[512 + oi];
        for (int j = 0; j < 256; ++j) {
            float v = h_ex[r * 260 + j];
            float e = (v > 0.f) ? v : (__expf(v) - 1.f);
            s += e * wout_sm[oi * 256 + j];
        }
        out[(size_t)oi * 4096 + (b0 + r)] = s;
    }
}

// ---------------- launch ----------------
extern "C" void kernel_launch(void* const* d_in, const int* in_sizes, int n_in,
                              void* d_out, int out_size) {
    const float* w     = (const float*)d_in[0];
    const float* W_ih  = (const float*)d_in[1];
    const float* W_hh  = (const float*)d_in[2];
    const float* b_ih  = (const float*)d_in[3];
    const float* b_hh  = (const float*)d_in[4];
    const float* W_out = (const float*)d_in[5];
    const float* b_out = (const float*)d_in[6];
    float* out = (float*)d_out;

    prep_kernel<<<256, 256>>>(W_ih, W_hh, b_ih, b_hh);

    cudaFuncSetAttribute(lstm_kernel, cudaFuncAttributeMaxDynamicSharedMemorySize, SMEM_BYTES);
    lstm_kernel<<<NCTA, 256, SMEM_BYTES>>>(w, W_out, b_out, out);
}

// round 11
// speedup vs baseline: 3.6358x; 1.4356x over previous
#include <cuda_runtime.h>
#include <cuda_fp16.h>
#include <mma.h>
#include <cstdint>

using namespace nvcuda;

// Problem dims
#define BATCH 4096
#define TSTEPS 365
#define FDIM 16
#define MT 32              // batch rows per CTA
#define NCTA (BATCH/MT)    // 128
#define KAUG 272           // 256 (h) + 16 (x)
#define NCHUNK 17          // 272 / 16
#define RING 4

// strides (elements)
#define LDHH 280           // h row stride in halves (272 + 8 pad)
#define WBH  72            // W chunk row stride in halves (64 + 8 pad)
#define SCR_LD 68          // gate scratch row stride (floats)

// per-warp W region: RING slots of 16*WBH halves
#define SLOT_H   (16*WBH)                  // 1152 halves = 2304 B
#define WREG_B   (RING*SLOT_H*2)           // 9216 B  (>= 32*68*4 = 8704 scratch)

// SMEM byte offsets (16B aligned)
#define OFF_HH   0                         // 32 x 280 halves = 17920
#define OFF_BIAS 17920                     // 1024 floats = 4096
#define OFF_WOUT 22016                     // 520 floats = 2080
#define OFF_SH   24096                     // 16 warps x 9216
#define SMEM_BYTES (OFF_SH + 16*WREG_B)    // 171552

// ---------------- device globals (preprocessed weights) ----------------
// g_Waug[k][n'] : rows 0..255 = W_hh^T, rows 256..271 = W_ih^T
// n' gate-interleaved (n' = j*4 + gate), fp16
__device__ __align__(256) __half g_Waug[KAUG * 1024];
__device__ float g_biasP[1024];

__global__ void prep_kernel(const float* __restrict__ W_ih,
                            const float* __restrict__ W_hh,
                            const float* __restrict__ b_ih,
                            const float* __restrict__ b_hh) {
    int tid = blockIdx.x * blockDim.x + threadIdx.x;
    int stride = gridDim.x * blockDim.x;
    for (int o = tid; o < KAUG * 1024; o += stride) {
        int k = o >> 10, np = o & 1023;
        int gate = np & 3, j = np >> 2;
        int n = gate * 256 + j;
        float v = (k < 256) ? W_hh[n * 256 + k] : W_ih[n * 16 + (k - 256)];
        g_Waug[o] = __float2half_rn(v);
    }
    for (int o = tid; o < 1024; o += stride) {
        int gate = o & 3, j = o >> 2;
        int n = gate * 256 + j;
        g_biasP[o] = b_ih[n] + b_hh[n];
    }
}

// ---------------- helpers ----------------
__device__ __forceinline__ void cp_async16(void* smem_dst, const void* gsrc) {
    unsigned saddr = (unsigned)__cvta_generic_to_shared(smem_dst);
    asm volatile("cp.async.cg.shared.global [%0], [%1], 16;\n" :: "r"(saddr), "l"(gsrc));
}
__device__ __forceinline__ void cp_commit() { asm volatile("cp.async.commit_group;\n"); }
__device__ __forceinline__ void cp_wait3()  { asm volatile("cp.async.wait_group 3;\n"); }

// sigmoid via HW tanh: 1 MUFU + 2 FMA
__device__ __forceinline__ float sig_approx(float x) {
    float t;
    asm("tanh.approx.f32 %0, %1;" : "=f"(t) : "f"(0.5f * x));
    return fmaf(0.5f, t, 0.5f);
}
// accurate tanh (EX2 + RCP): used where error feeds output directly
__device__ __forceinline__ float tanhf_fast(float x) {
    x = fminf(fmaxf(x, -15.f), 15.f);
    float e = __expf(-2.f * x);
    return __fdividef(1.f - e, 1.f + e);
}

// stage one 16x64 fp16 W chunk (warp-private slice): 2KB = 4 x 16B per lane
__device__ __forceinline__ void stage_chunk(__half* wbuf, int kc, int cg, int ln) {
#pragma unroll
    for (int it = 0; it < 4; ++it) {
        int lin = it * 32 + ln;          // 0..127
        int row = lin >> 3;              // 0..15
        int c8  = lin & 7;               // 0..7 (16B groups)
        cp_async16(wbuf + row * WBH + c8 * 8,
                   &g_Waug[(size_t)(kc * 16 + row) * 1024 + cg * 64 + c8 * 8]);
    }
}

// ---------------- main persistent LSTM kernel ----------------
__global__ void __launch_bounds__(512, 1)
lstm_kernel(const float* __restrict__ w,
            const float* __restrict__ W_out,
            const float* __restrict__ b_out,
            float* __restrict__ out) {
    extern __shared__ char smb[];
    __half* h_h    = (__half*)(smb + OFF_HH);   // [32][LDHH]: cols 0..255 = h, 256..271 = x_t
    float*  bias_sm= (float*)(smb + OFF_BIAS);
    float*  wout_sm= (float*)(smb + OFF_WOUT);

    const int tid = threadIdx.x;
    const int cg  = tid >> 5;            // warp = col slice: perm cols [cg*64,+64) = units [cg*16,+16)
    const int ln  = tid & 31;
    const int b0  = blockIdx.x * MT;

    // init
    for (int i = tid; i < MT * LDHH; i += 512) h_h[i] = __float2half_rn(0.f);
    for (int i = tid; i < 1024; i += 512) bias_sm[i] = g_biasP[i];
    if (tid < 512 && tid < 512) {}
    for (int i = tid; i < 512; i += 512) wout_sm[i] = W_out[i];
    if (tid < 2) wout_sm[512 + tid] = b_out[tid];
    __syncthreads();

    __half* wreg = (__half*)(smb + OFF_SH + cg * WREG_B);  // RING slots, warp-private
    float*  scr  = (float*)wreg;                           // 32 x SCR_LD, aliases ring

    // cell state: lane owns 4 rows x 4 units = 16 cells
    float creg[16];
#pragma unroll
    for (int i = 0; i < 16; i++) creg[i] = 0.f;

    const int rbase = (ln >> 2) * 4;    // local row base (0,4,...,28)
    const int ub    = ln & 3;           // unit base (units ub, ub+4, ub+8, ub+12)

    // preload bias for my 4 units
    float4 bv[4];
#pragma unroll
    for (int uu = 0; uu < 4; ++uu)
        bv[uu] = *reinterpret_cast<const float4*>(bias_sm + (cg * 16 + ub + uu * 4) * 4);

    wmma::fragment<wmma::accumulator, 16, 16, 16, float> acc0[4], acc1[4];

    for (int t = 0; t < TSTEPS; ++t) {
        // stage x_t into h_h K-cols 256..271 (fp16) — exactly 1 elem per thread
        {
            int r = tid >> 4, f = tid & 15;
            h_h[r * LDHH + 256 + f] =
                __float2half_rn(w[((size_t)(b0 + r) * TSTEPS + t) * FDIM + f]);
        }
        __syncthreads();  // B0: h(t-1) + x(t) visible to all; scratch/ring free

        // prefetch ring: chunks 0..2
        stage_chunk(wreg + 0 * SLOT_H, 0, cg, ln); cp_commit();
        stage_chunk(wreg + 1 * SLOT_H, 1, cg, ln); cp_commit();
        stage_chunk(wreg + 2 * SLOT_H, 2, cg, ln); cp_commit();

#pragma unroll
        for (int i = 0; i < 4; i++) { wmma::fill_fragment(acc0[i], 0.f); wmma::fill_fragment(acc1[i], 0.f); }

        // [h|x] @ Waug : K=272, 17 chunks of 16, ring-4, depth-3 prefetch, NO barriers
        for (int kc = 0; kc < NCHUNK; ++kc) {
            __half* cur = wreg + (kc & 3) * SLOT_H;
            if (kc + 3 < NCHUNK) stage_chunk(wreg + ((kc + 3) & 3) * SLOT_H, kc + 3, cg, ln);
            cp_commit();          // empty group on tail iters keeps count uniform
            cp_wait3();           // chunk kc resident
            __syncwarp();
            wmma::fragment<wmma::matrix_a, 16, 16, 16, __half, wmma::row_major> a0, a1;
            wmma::load_matrix_sync(a0, h_h + kc * 16, LDHH);
            wmma::load_matrix_sync(a1, h_h + 16 * LDHH + kc * 16, LDHH);
#pragma unroll
            for (int i = 0; i < 4; i++) {
                wmma::fragment<wmma::matrix_b, 16, 16, 16, __half, wmma::row_major> bf;
                wmma::load_matrix_sync(bf, cur + i * 16, WBH);
                wmma::mma_sync(acc0[i], a0, bf, acc0[i]);
                wmma::mma_sync(acc1[i], a1, bf, acc1[i]);
            }
        }
        __syncthreads();  // B1: all h reads done before epilogue writes h

        // epilogue: warp-private scratch (aliases own ring), no cross-warp sync
#pragma unroll
        for (int i = 0; i < 4; i++) {
            wmma::store_matrix_sync(scr + i * 16, acc0[i], SCR_LD, wmma::mem_row_major);
            wmma::store_matrix_sync(scr + 16 * SCR_LD + i * 16, acc1[i], SCR_LD, wmma::mem_row_major);
        }
        __syncwarp();
#pragma unroll
        for (int rr = 0; rr < 4; ++rr) {
            const int r = rbase + rr;
#pragma unroll
            for (int uu = 0; uu < 4; ++uu) {
                const int ul = ub + uu * 4;               // local unit 0..15
                float4 gv = *reinterpret_cast<float4*>(scr + r * SCR_LD + ul * 4);
                float gi = sig_approx(gv.x + bv[uu].x);
                float gf = sig_approx(gv.y + bv[uu].y);
                float gg = tanhf_fast(gv.z + bv[uu].z);
                float go = sig_approx(gv.w + bv[uu].w);
                const int ci = rr * 4 + uu;
                float c = gf * creg[ci] + gi * gg;
                creg[ci] = c;
                float hn = go * tanhf_fast(c);
                const int jg = cg * 16 + ul;              // hidden unit 0..255
                h_h[r * LDHH + jg] = __float2half_rn(hn);
                if (t == TSTEPS - 1)
                    out[8192 + (size_t)(b0 + r) * 256 + jg] = hn;
            }
        }
    }
    __syncthreads();  // final h (in out[]) visible CTA-wide

    // head: tz0 = ELU(h) @ W_out^T + b_out  (exact fp32; h read back from out)
    if (tid < 64) {
        const int r = tid >> 1, oi = tid & 1;
        const float* hrow = out + 8192 + (size_t)(b0 + r) * 256;
        float s = wout_sm[512 + oi];
#pragma unroll 8
        for (int j = 0; j < 256; ++j) {
            float v = hrow[j];
            float e = (v > 0.f) ? v : (__expf(v) - 1.f);
            s = fmaf(e, wout_sm[oi * 256 + j], s);
        }
        out[(size_t)oi * 4096 + (b0 + r)] = s;
    }
}

// ---------------- launch ----------------
extern "C" void kernel_launch(void* const* d_in, const int* in_sizes, int n_in,
                              void* d_out, int out_size) {
    const float* w     = (const float*)d_in[0];
    const float* W_ih  = (const float*)d_in[1];
    const float* W_hh  = (const float*)d_in[2];
    const float* b_ih  = (const float*)d_in[3];
    const float* b_hh  = (const float*)d_in[4];
    const float* W_out = (const float*)d_in[5];
    const float* b_out = (const float*)d_in[6];
    float* out = (float*)d_out;

    prep_kernel<<<256, 256>>>(W_ih, W_hh, b_ih, b_hh);

    cudaFuncSetAttribute(lstm_kernel, cudaFuncAttributeMaxDynamicSharedMemorySize, SMEM_BYTES);
    lstm_kernel<<<NCTA, 512, SMEM_BYTES>>>(w, W_out, b_out, out);
}

// round 12
// speedup vs baseline: 4.8122x; 1.3236x over previous
#include <cuda_runtime.h>
#include <cuda_fp16.h>
#include <cstdint>

// Problem dims
#define BATCH 4096
#define TSTEPS 365
#define FDIM 16
#define MT 32              // batch rows per CTA
#define NCTA (BATCH/MT)    // 128
#define NCHUNK 17          // K=272 / 16
#define NPER 2             // persistent chunks (0,1)

// strides (elements)
#define LDHH 280           // h row stride in halves (272 + 8 pad); 560B = 16*35 (ldmatrix-aligned)
#define WBH  72            // W chunk row stride in halves (64 + 8 pad); 144B
#define SLOT_H (16*WBH)    // 1152 halves = 2304 B per chunk slot
#define WREG_B (5*SLOT_H*2)// 11520 B per warp: 2 persistent + 3 ring slots

// SMEM byte offsets (16B aligned)
#define OFF_HH   0                         // 32 x 280 halves = 17920
#define OFF_BIAS 17920                     // 1024 floats = 4096
#define OFF_WOUT 22016                     // 520 floats -> 2112
#define OFF_SH   24128                     // 16 warps x 11520 = 184320
#define SMEM_BYTES (OFF_SH + 16*WREG_B)    // 208448

// ---------------- device globals (preprocessed weights) ----------------
// g_Waug[k][n'] : rows 0..255 = W_hh^T, rows 256..271 = W_ih^T
// n' gate-interleaved (n' = j*4 + gate), fp16
__device__ __align__(256) __half g_Waug[272 * 1024];
__device__ float g_biasP[1024];

__global__ void prep_kernel(const float* __restrict__ W_ih,
                            const float* __restrict__ W_hh,
                            const float* __restrict__ b_ih,
                            const float* __restrict__ b_hh) {
    int tid = blockIdx.x * blockDim.x + threadIdx.x;
    int stride = gridDim.x * blockDim.x;
    for (int o = tid; o < 272 * 1024; o += stride) {
        int k = o >> 10, np = o & 1023;
        int gate = np & 3, j = np >> 2;
        int n = gate * 256 + j;
        float v = (k < 256) ? W_hh[n * 256 + k] : W_ih[n * 16 + (k - 256)];
        g_Waug[o] = __float2half_rn(v);
    }
    for (int o = tid; o < 1024; o += stride) {
        int gate = o & 3, j = o >> 2;
        int n = gate * 256 + j;
        g_biasP[o] = b_ih[n] + b_hh[n];
    }
}

// ---------------- helpers ----------------
__device__ __forceinline__ void cp_async16(void* smem_dst, const void* gsrc) {
    unsigned saddr = (unsigned)__cvta_generic_to_shared(smem_dst);
    asm volatile("cp.async.cg.shared.global [%0], [%1], 16;\n" :: "r"(saddr), "l"(gsrc));
}
__device__ __forceinline__ void cp_commit() { asm volatile("cp.async.commit_group;\n"); }
__device__ __forceinline__ void cp_wait0()  { asm volatile("cp.async.wait_group 0;\n"); }
__device__ __forceinline__ void cp_wait2()  { asm volatile("cp.async.wait_group 2;\n"); }

__device__ __forceinline__ float tanh_raw(float x) {
    float t; asm("tanh.approx.f32 %0, %1;" : "=f"(t) : "f"(x)); return t;
}
// sigmoid via HW tanh: 1 MUFU + FMA
__device__ __forceinline__ float sig_approx(float x) {
    return fmaf(0.5f, tanh_raw(0.5f * x), 0.5f);
}
// accurate tanh (EX2 + RCP): output-critical path only
__device__ __forceinline__ float tanhf_fast(float x) {
    x = fminf(fmaxf(x, -15.f), 15.f);
    float e = __expf(-2.f * x);
    return __fdividef(1.f - e, 1.f + e);
}

__device__ __forceinline__ void ldsm_x4(uint32_t* r, const __half* p) {
    uint32_t a = (uint32_t)__cvta_generic_to_shared(p);
    asm volatile("ldmatrix.sync.aligned.m8n8.x4.shared.b16 {%0,%1,%2,%3}, [%4];"
                 : "=r"(r[0]), "=r"(r[1]), "=r"(r[2]), "=r"(r[3]) : "r"(a));
}
__device__ __forceinline__ void ldsm_x4t(uint32_t* r, const __half* p) {
    uint32_t a = (uint32_t)__cvta_generic_to_shared(p);
    asm volatile("ldmatrix.sync.aligned.m8n8.x4.trans.shared.b16 {%0,%1,%2,%3}, [%4];"
                 : "=r"(r[0]), "=r"(r[1]), "=r"(r[2]), "=r"(r[3]) : "r"(a));
}
__device__ __forceinline__ void mma16816(float* d, const uint32_t* a, const uint32_t* b) {
    asm volatile("mma.sync.aligned.m16n8k16.row.col.f32.f16.f16.f32 "
                 "{%0,%1,%2,%3}, {%4,%5,%6,%7}, {%8,%9}, {%0,%1,%2,%3};"
                 : "+f"(d[0]), "+f"(d[1]), "+f"(d[2]), "+f"(d[3])
                 : "r"(a[0]), "r"(a[1]), "r"(a[2]), "r"(a[3]), "r"(b[0]), "r"(b[1]));
}

// stage one 16x64 fp16 W chunk (warp-private slice): 2KB = 4 x 16B per lane
__device__ __forceinline__ void stage_chunk(__half* wbuf, int kc, int cg, int ln) {
#pragma unroll
    for (int it = 0; it < 4; ++it) {
        int lin = it * 32 + ln;          // 0..127
        int row = lin >> 3;              // 0..15
        int c8  = lin & 7;               // 0..7 (16B groups)
        cp_async16(wbuf + row * WBH + c8 * 8,
                   &g_Waug[(size_t)(kc * 16 + row) * 1024 + cg * 64 + c8 * 8]);
    }
}

// one K=16 chunk: 2 A ldmatrix + 4 B ldmatrix.trans + 16 HMMA
__device__ __forceinline__ void do_chunk(float (*acc)[8][4], const __half* h_h,
                                         const __half* cur, int kc,
                                         uint32_t aoff0, uint32_t boff) {
    uint32_t a0[4], a1[4];
    ldsm_x4(a0, h_h + kc * 16 + aoff0);
    ldsm_x4(a1, h_h + kc * 16 + aoff0 + 16 * LDHH);
#pragma unroll
    for (int nt2 = 0; nt2 < 4; ++nt2) {
        uint32_t b[4];
        ldsm_x4t(b, cur + boff + nt2 * 16);
        mma16816(acc[0][nt2 * 2],     a0, b);
        mma16816(acc[0][nt2 * 2 + 1], a0, b + 2);
        mma16816(acc[1][nt2 * 2],     a1, b);
        mma16816(acc[1][nt2 * 2 + 1], a1, b + 2);
    }
}

// ---------------- main persistent LSTM kernel ----------------
__global__ void __launch_bounds__(512, 1)
lstm_kernel(const float* __restrict__ w,
            const float* __restrict__ W_out,
            const float* __restrict__ b_out,
            float* __restrict__ out) {
    extern __shared__ char smb[];
    __half* h_h    = (__half*)(smb + OFF_HH);   // [32][LDHH]: cols 0..255 = h, 256..271 = x_t
    float*  bias_sm= (float*)(smb + OFF_BIAS);
    float*  wout_sm= (float*)(smb + OFF_WOUT);

    const int tid = threadIdx.x;
    const int cg  = tid >> 5;            // warp = col slice: perm cols [cg*64,+64) = units [cg*16,+16)
    const int ln  = tid & 31;
    const int q   = ln & 3;
    const int b0  = blockIdx.x * MT;

    __half* persist = (__half*)(smb + OFF_SH + cg * WREG_B);
    __half* ring    = persist + NPER * SLOT_H;

    // init: h=0, x(0), bias, wout
    for (int i = tid; i < MT * LDHH; i += 512) h_h[i] = __float2half_rn(0.f);
    for (int i = tid; i < 1024; i += 512) bias_sm[i] = g_biasP[i];
    for (int i = tid; i < 512; i += 512) wout_sm[i] = W_out[i];
    if (tid < 2) wout_sm[512 + tid] = b_out[tid];
    {
        int r = tid >> 4, f = tid & 15;
        h_h[r * LDHH + 256 + f] =
            __float2half_rn(w[((size_t)(b0 + r) * TSTEPS + 0) * FDIM + f]);
    }
    // persistent chunks 0,1 (warp-private)
    stage_chunk(persist,          0, cg, ln);
    stage_chunk(persist + SLOT_H, 1, cg, ln);
    cp_commit(); cp_wait0(); __syncwarp();
    // ring prologue: chunks 2,3 -> slots 0,1 (depth-2 stream starts)
    stage_chunk(ring,          2, cg, ln); cp_commit();
    stage_chunk(ring + SLOT_H, 3, cg, ln); cp_commit();

    // lane constants
    const uint32_t aoff0 = (uint32_t)((ln & 15) * LDHH + (ln >> 4) * 8);
    const uint32_t boff  = (uint32_t)((ln & 15) * WBH  + (ln >> 4) * 8);
    const float m0  = (q & 1) ? 1.0f : 0.5f;   // gate0 = g (tanh) on odd, i (sigmoid) on even
    const float a0c = (q & 1) ? 0.0f : 0.5f;
    const int row_l = (ln >> 2) + ((q & 1) << 3);   // owned row within 16-tile

    float creg[16];
#pragma unroll
    for (int i = 0; i < 16; i++) creg[i] = 0.f;

    for (int t = 0; t < TSTEPS; ++t) {
        __syncthreads();  // B0: h(t) + x(t) visible to all warps
        // hoist next x load (consumed after B1)
        float xnext = 0.f;
        if (t + 1 < TSTEPS)
            xnext = w[((size_t)(b0 + (tid >> 4)) * TSTEPS + t + 1) * FDIM + (tid & 15)];

        float acc[2][8][4];
#pragma unroll
        for (int mt = 0; mt < 2; ++mt)
#pragma unroll
            for (int nt = 0; nt < 8; ++nt)
#pragma unroll
                for (int v = 0; v < 4; ++v) acc[mt][nt][v] = 0.f;

        // persistent chunks 0,1
        do_chunk(acc, h_h, persist,          0, aoff0, boff);
        do_chunk(acc, h_h, persist + SLOT_H, 1, aoff0, boff);

        // streamed chunks 2..16: ring-3, depth-2, continuous across steps
#pragma unroll 3
        for (int kc = 2; kc < NCHUNK; ++kc) {
            int kn = (kc <= 14) ? kc + 2 : kc - 13;   // next chunk (wraps into next step)
            stage_chunk(ring + (kc % 3) * SLOT_H, kn, cg, ln);
            cp_commit();
            cp_wait2();          // chunk kc resident
            __syncwarp();
            do_chunk(acc, h_h, ring + ((kc - 2) % 3) * SLOT_H, kc, aoff0, boff);
        }
        __syncthreads();  // B1: all h/x reads done before h/x writes

        // stage x(t+1)
        h_h[(tid >> 4) * LDHH + 256 + (tid & 15)] = __float2half_rn(xnext);

        // register epilogue: gate exchange via shfl, no smem scratch
#pragma unroll
        for (int mt = 0; mt < 2; ++mt) {
#pragma unroll
            for (int nt = 0; nt < 8; ++nt) {
                float2 bv = *(const float2*)(bias_sm + cg * 64 + nt * 8 + 2 * q);
                float* d = acc[mt][nt];
                float pA0 = d[0] + bv.x, pA1 = d[1] + bv.y;   // row rA = l/4
                float pB0 = d[2] + bv.x, pB1 = d[3] + bv.y;   // row rB = l/4+8
                // gate0: even lanes sigmoid(i), odd lanes tanh(g) — branchless
                float e0A = fmaf(tanh_raw(pA0 * m0), m0, a0c);
                float e1A = sig_approx(pA1);                   // f (even) / o (odd)
                float e0B = fmaf(tanh_raw(pB0 * m0), m0, a0c);
                float e1B = sig_approx(pB1);
                // exchange: even owns row A, odd owns row B
                bool odd = (q & 1);
                float sx = odd ? e0A : e0B;
                float sy = odd ? e1A : e1B;
                float rx = __shfl_xor_sync(0xffffffffu, sx, 1);
                float ry = __shfl_xor_sync(0xffffffffu, sy, 1);
                float si = odd ? rx  : e0A;
                float sf = odd ? ry  : e1A;
                float tg = odd ? e0B : rx;
                float so = odd ? e1B : ry;
                const int ci = mt * 8 + nt;
                float c = fmaf(sf, creg[ci], si * tg);
                creg[ci] = c;
                float hn = so * tanhf_fast(c);
                const int row = mt * 16 + row_l;
                const int j   = cg * 16 + nt * 2 + (q >> 1);
                h_h[row * LDHH + j] = __float2half_rn(hn);
                if (t == TSTEPS - 1)
                    out[8192 + (size_t)(b0 + row) * 256 + j] = hn;
            }
        }
    }
    cp_wait0();
    __syncthreads();  // final h (in out[]) visible CTA-wide

    // head: tz0 = ELU(h) @ W_out^T + b_out  (exact fp32; h read back from out)
    if (tid < 64) {
        const int r = tid >> 1, oi = tid & 1;
        const float* hrow = out + 8192 + (size_t)(b0 + r) * 256;
        float s = wout_sm[512 + oi];
#pragma unroll 8
        for (int j = 0; j < 256; ++j) {
            float v = hrow[j];
            float e = (v > 0.f) ? v : (__expf(v) - 1.f);
            s = fmaf(e, wout_sm[oi * 256 + j], s);
        }
        out[(size_t)oi * 4096 + (b0 + r)] = s;
    }
}

// ---------------- launch ----------------
extern "C" void kernel_launch(void* const* d_in, const int* in_sizes, int n_in,
                              void* d_out, int out_size) {
    const float* w     = (const float*)d_in[0];
    const float* W_ih  = (const float*)d_in[1];
    const float* W_hh  = (const float*)d_in[2];
    const float* b_ih  = (const float*)d_in[3];
    const float* b_hh  = (const float*)d_in[4];
    const float* W_out = (const float*)d_in[5];
    const float* b_out = (const float*)d_in[6];
    float* out = (float*)d_out;

    prep_kernel<<<256, 256>>>(W_ih, W_hh, b_ih, b_hh);

    cudaFuncSetAttribute(lstm_kernel, cudaFuncAttributeMaxDynamicSharedMemorySize, SMEM_BYTES);
    lstm_kernel<<<NCTA, 512, SMEM_BYTES>>>(w, W_out, b_out, out);
}